// round 13
// baseline (speedup 1.0000x reference)
#include <cuda_runtime.h>
#include <math.h>

#define NB 16      // batch
#define NV 778     // verts
#define NO 8192    // obj points
#define NG 32      // groups
#define NKNN 5     // K
#define BLK 128    // threads per block (k_main)
#define VCHUNKS 7  // ceil(778/128)
#define VP (VCHUNKS * BLK)     // 896 padded vertices
#define OSPLIT 16
#define OTILE (NO / OSPLIT)    // 512 points per block
#define HTILE (OTILE / 2)      // 256 pairs
#define NPART (VCHUNKS * NB)   // 112 partial slots
#define MBLK 256               // k_merge threads (2 halves of 128)

#define C3LOG2PI 5.5136313438f  // fp32(3.0 * log(2*pi))

// ---------------- device scratch (no allocation allowed) ----------------
__device__ int      g_gid[NV];
__device__ float    g_prep[NB * NG * 10];
__device__ int      g_active[NG];
__device__ unsigned g_segmin[NB * NG];
__device__ unsigned g_segmax[NB * NG];
__device__ float    g_w[NB * NV];
// coalesced split partials: k5[((os*NB+b)*5+i)*VP+vp], bs/bi[(os*NB+b)*VP+vp]
__device__ float    g_k5[OSPLIT * NB * 5 * VP];
__device__ float    g_bs[OSPLIT * NB * VP];
__device__ int      g_bi[OSPLIT * NB * VP];
__device__ float    g_part_d[NPART];
__device__ float    g_part_p[NPART];
__device__ unsigned g_ticket = 0;

// ---------------- packed f32x2 helpers (sm_103a FFMA2) ----------------
__device__ __forceinline__ unsigned long long pk2(float a, float b) {
    unsigned long long r;
    asm("mov.b64 %0, {%1,%2};" : "=l"(r) : "f"(a), "f"(b));
    return r;
}
__device__ __forceinline__ unsigned long long fma2(unsigned long long a,
                                                   unsigned long long b,
                                                   unsigned long long c) {
    unsigned long long d;
    asm("fma.rn.f32x2 %0, %1, %2, %3;" : "=l"(d) : "l"(a), "l"(b), "l"(c));
    return d;
}
__device__ __forceinline__ void upk2(unsigned long long r, float& lo, float& hi) {
    asm("mov.b64 {%0,%1}, %2;" : "=f"(lo), "=f"(hi) : "l"(r));
}

__device__ __forceinline__ void ins5(float s, float& k0, float& k1, float& k2,
                                     float& k3, float& k4) {
    k4 = s;
    if (k4 < k3) { float t = k3; k3 = k4; k4 = t;
        if (k3 < k2) { t = k2; k2 = k3; k3 = t;
            if (k2 < k1) { t = k1; k1 = k2; k2 = t;
                if (k1 < k0) { t = k0; k0 = k1; k1 = t; } } } }
}

// ---------------- kernel 1: parallel setup (gid | prep | active) ----------------
// grid 12 x 128: blocks 0-6 gid, blocks 7-10 Cholesky prep + seg init, block 11 active flags
__global__ void __launch_bounds__(128) k_setup(const float* __restrict__ init_verts,
                                               const float* __restrict__ init_anchors,
                                               const float* __restrict__ cg,
                                               const float* __restrict__ anchor_verts) {
    int bid = blockIdx.x;
    int t = threadIdx.x;

    if (bid < 7) {
        // ---- vertex -> group assignment ----
        int v = bid * 128 + t;
        if (v < NV) {
            float ax = init_verts[3 * v + 0];
            float ay = init_verts[3 * v + 1];
            float az = init_verts[3 * v + 2];
            float a2 = ax * ax + ay * ay + az * az;
            float best = INFINITY;
            int bi = 0;
            #pragma unroll
            for (int g = 0; g < NG; g++) {
                float bx = init_anchors[3 * g + 0];
                float by = init_anchors[3 * g + 1];
                float bz = init_anchors[3 * g + 2];
                float b2 = bx * bx + by * by + bz * bz;
                float d2 = a2 + b2 - 2.0f * (ax * bx + ay * by + az * bz);
                if (d2 < best) { best = d2; bi = g; }   // strict < : first min
            }
            g_gid[v] = bi;
        }
    } else if (bid < 11) {
        // ---- per-(b,g) Cholesky prep + segment init ----
        int idx = (bid - 7) * 128 + t;   // 0..511
        g_segmin[idx] = 0x7F800000u;     // +inf
        g_segmax[idx] = 0u;              // +0.0

        const float* c = cg + idx * 12;
        float c00 = c[3], c10 = c[6], c11 = c[7], c20 = c[9], c21 = c[10], c22 = c[11];
        float L00 = sqrtf(c00);
        float L10 = c10 / L00;
        float L20 = c20 / L00;
        float L11 = sqrtf(c11 - L10 * L10);
        float L21 = (c21 - L20 * L10) / L11;
        float L22 = sqrtf(c22 - L20 * L20 - L21 * L21);
        float hld = logf(L00) + logf(L11) + logf(L22);

        float* P = g_prep + idx * 10;
        P[0] = L00; P[1] = L10; P[2] = L11;
        P[3] = L20; P[4] = L21; P[5] = L22;
        P[6] = c[0] + anchor_verts[idx * 3 + 0];
        P[7] = c[1] + anchor_verts[idx * 3 + 1];
        P[8] = c[2] + anchor_verts[idx * 3 + 2];
        P[9] = hld;
    } else {
        // ---- active flags: direct per-g reduction (no atomics, no reset race) ----
        if (t < NG) {
            int act = 0;
            for (int b = 0; b < NB; b++) {
                const float* c = cg + (b * NG + t) * 12;
                #pragma unroll
                for (int i = 0; i < 12; i++) act |= (fabsf(c[i]) > 1e-9f);
            }
            g_active[t] = act;
        }
    }
}

// ---------------- kernel 2: Gaussian weights + segment min/max ----------------
__global__ void k_weights(const float* __restrict__ verts) {
    int i = blockIdx.x * blockDim.x + threadIdx.x;
    if (i >= NB * NV) return;
    int b = i / NV;
    int v = i % NV;
    int g = g_gid[v];
    const float* P = g_prep + (b * NG + g) * 10;
    float dx = verts[3 * i + 0] - P[6];
    float dy = verts[3 * i + 1] - P[7];
    float dz = verts[3 * i + 2] - P[8];
    float y0 = dx / P[0];
    float y1 = (dy - P[1] * y0) / P[2];
    float y2 = (dz - P[3] * y0 - P[4] * y1) / P[5];
    float maha = y0 * y0 + y1 * y1 + y2 * y2;
    float logp = -0.5f * (maha + C3LOG2PI) - P[9];
    float w = expf(logp);
    g_w[i] = w;
    unsigned wb = __float_as_uint(w);
    atomicMin(&g_segmin[b * NG + g], wb);
    atomicMax(&g_segmax[b * NG + g], wb);
}

// ---------------- kernel 3: split KNN + nearest-normal sweep (R6 body) ----------------
__global__ void __launch_bounds__(BLK) k_main(const float* __restrict__ verts,
                                              const float* __restrict__ obj_pts,
                                              const float* __restrict__ obj_nrm) {
    // packed-pair layout: sP[h] = { pack(x'0,x'1), pack(y'0,y'1) },
    //                     sPw[h] = { pack(z'0,z'1), pack(w0,w1) },  x' = -2x
    __shared__ ulonglong2 sP[HTILE],  sPw[HTILE];   // obj points
    __shared__ ulonglong2 sN[HTILE],  sNw[HTILE];   // normal points

    int b  = blockIdx.y;
    int os = blockIdx.z;
    int vp = blockIdx.x * BLK + threadIdx.x;

    float ax = 0.f, ay = 0.f, az = 0.f;
    if (vp < NV) {
        int i = b * NV + vp;
        ax = verts[3 * i + 0]; ay = verts[3 * i + 1]; az = verts[3 * i + 2];
    }

    int base = os * OTILE;
    const float* OP = obj_pts + (size_t)b * NO * 3;
    const float* ON = obj_nrm + (size_t)b * NO * 6;

    for (int j = threadIdx.x; j < OTILE; j += BLK) {
        int o = base + j;
        int h = j >> 1, e = j & 1;
        float x = OP[3 * o + 0], y = OP[3 * o + 1], z = OP[3 * o + 2];
        float* P  = (float*)&sP[h];
        float* Pw = (float*)&sPw[h];
        P[e]      = -2.0f * x;
        P[2 + e]  = -2.0f * y;
        Pw[e]     = -2.0f * z;
        Pw[2 + e] = x * x + y * y + z * z;
        float nx = ON[6 * o + 0], ny = ON[6 * o + 1], nz = ON[6 * o + 2];
        float* N  = (float*)&sN[h];
        float* Nw = (float*)&sNw[h];
        N[e]      = -2.0f * nx;
        N[2 + e]  = -2.0f * ny;
        Nw[e]     = -2.0f * nz;
        Nw[2 + e] = nx * nx + ny * ny + nz * nz;
    }
    __syncthreads();

    unsigned long long AX = pk2(ax, ax), AY = pk2(ay, ay), AZ = pk2(az, az);

    float k0 = INFINITY, k1 = INFINITY, k2 = INFINITY, k3 = INFINITY, k4 = INFINITY;
    float best = INFINITY;
    int   bidx = base;

    #pragma unroll 4
    for (int h = 0; h < HTILE; h++) {
        ulonglong2 A  = sP[h];    // broadcast LDS.128 -> two packed operands
        ulonglong2 Aw = sPw[h];
        unsigned long long r = fma2(AZ, Aw.x, Aw.y);
        r = fma2(AY, A.y, r);
        r = fma2(AX, A.x, r);
        float s0, s1; upk2(r, s0, s1);
        float m = fminf(s0, s1);
        if (m < k4) {                       // rare
            if (s0 < k4) ins5(s0, k0, k1, k2, k3, k4);
            if (s1 < k4) ins5(s1, k0, k1, k2, k3, k4);
        }

        ulonglong2 C  = sN[h];
        ulonglong2 Cw = sNw[h];
        unsigned long long q = fma2(AZ, Cw.x, Cw.y);
        q = fma2(AY, C.y, q);
        q = fma2(AX, C.x, q);
        float n0, n1; upk2(q, n0, n1);
        float mn = fminf(n0, n1);
        if (mn < best) {                    // rare
            if (n0 < best) { best = n0; bidx = base + 2 * h; }
            if (n1 < best) { best = n1; bidx = base + 2 * h + 1; }
        }
    }

    int sbase = (os * NB + b);
    float* K = g_k5 + (size_t)sbase * 5 * VP + vp;
    K[0 * VP] = k0; K[1 * VP] = k1; K[2 * VP] = k2; K[3 * VP] = k3; K[4 * VP] = k4;
    g_bs[(size_t)sbase * VP + vp] = best;
    g_bi[(size_t)sbase * VP + vp] = bidx;
}

// ---------------- kernel 4: 2-way-split merge + epilogue + deterministic finish ----------------
// 256 threads: lower 128 merge splits 0-7, upper 128 merge splits 8-15; combine via smem.
__global__ void __launch_bounds__(MBLK) k_merge(const float* __restrict__ verts,
                                                const float* __restrict__ obj_nrm,
                                                float* __restrict__ out, int out_size) {
    __shared__ float  sK[128 * 5];
    __shared__ float  sBs[128];
    __shared__ int    sBi[128];
    __shared__ float2 red[MBLK];

    int b    = blockIdx.y;
    int half = threadIdx.x >> 7;        // 0 = splits 0-7, 1 = splits 8-15
    int lane = threadIdx.x & 127;
    int vp   = blockIdx.x * 128 + lane; // 0..895
    int os0  = half * 8;

    // ---- front-load this half's 8 splits (one latency wave) ----
    float kb[40];
    float bsb[8];
    int   bib[8];
    #pragma unroll
    for (int oss = 0; oss < 8; oss++) {
        const float* K = g_k5 + (size_t)((os0 + oss) * NB + b) * 5 * VP + vp;
        #pragma unroll
        for (int i = 0; i < 5; i++) kb[oss * 5 + i] = K[i * VP];   // coalesced
    }
    #pragma unroll
    for (int oss = 0; oss < 8; oss++) {
        size_t sl = (size_t)((os0 + oss) * NB + b) * VP + vp;
        bsb[oss] = g_bs[sl];
        bib[oss] = g_bi[sl];
    }

    // ---- half-merge: top-5 over 40 values (ascending split,i order) ----
    float m0 = INFINITY, m1 = INFINITY, m2 = INFINITY, m3 = INFINITY, m4 = INFINITY;
    #pragma unroll
    for (int j = 0; j < 40; j++) {
        float s = kb[j];
        if (s < m4) ins5(s, m0, m1, m2, m3, m4);
    }
    float hb = INFINITY; int hbi = 0;
    #pragma unroll
    for (int oss = 0; oss < 8; oss++) {
        if (bsb[oss] < hb) { hb = bsb[oss]; hbi = bib[oss]; }
    }

    // ---- upper half publishes its result ----
    if (half == 1) {
        sK[lane * 5 + 0] = m0; sK[lane * 5 + 1] = m1; sK[lane * 5 + 2] = m2;
        sK[lane * 5 + 3] = m3; sK[lane * 5 + 4] = m4;
        sBs[lane] = hb;
        sBi[lane] = hbi;
    }
    __syncthreads();

    float dpart = 0.0f, ppart = 0.0f;
    if (half == 0) {
        // combine: upper-half values inserted after lower (higher splits) — same ties
        #pragma unroll
        for (int i = 0; i < 5; i++) {
            float s = sK[lane * 5 + i];
            if (s < m4) ins5(s, m0, m1, m2, m3, m4);
        }
        float ub = sBs[lane];
        int   ubi = sBi[lane];
        if (ub < hb) { hb = ub; hbi = ubi; }   // strict < keeps lower split on ties

        bool act = (vp < NV);
        float ax = 0.f, ay = 0.f, az = 0.f, eff = 0.f;
        if (act) {
            int i = b * NV + vp;
            ax = verts[3 * i + 0];
            ay = verts[3 * i + 1];
            az = verts[3 * i + 2];
            int g = g_gid[vp];
            float w  = g_w[i];
            float mn = __uint_as_float(g_segmin[b * NG + g]);
            float mx = __uint_as_float(g_segmax[b * NG + g]);
            float wn = (w - mn) / (mx - mn);
            wn  = (wn > 0.01f) ? wn : 0.0f;     // NaN -> false -> 0 (matches jnp.where)
            eff = g_active[g] ? wn : 0.0f;
        }

        float va2 = ax * ax + ay * ay + az * az;
        float ksum = sqrtf(fmaxf(m0 + va2, 0.0f))
                   + sqrtf(fmaxf(m1 + va2, 0.0f))
                   + sqrtf(fmaxf(m2 + va2, 0.0f))
                   + sqrtf(fmaxf(m3 + va2, 0.0f))
                   + sqrtf(fmaxf(m4 + va2, 0.0f));
        dpart = eff * ksum;

        if (act) {
            const float* nn = obj_nrm + ((size_t)b * NO + hbi) * 6;
            float px = nn[0], py = nn[1], pz = nn[2];
            float nx = nn[3], ny = nn[4], nz = nn[5];
            float rx = px - 0.002f * nx;
            float ry = py - 0.002f * ny;
            float rz = pz - 0.002f * nz;
            float dp = nx * (ax - rx) + ny * (ay - ry) + nz * (az - rz);
            ppart = fmaxf(-dp, 0.0f);
        }
    }

    // block reduction (upper half contributes exact zeros -> bitwise-same sum)
    red[threadIdx.x] = make_float2(dpart, ppart);
    __syncthreads();
    for (int s = MBLK / 2; s > 0; s >>= 1) {
        if (threadIdx.x < s) {
            red[threadIdx.x].x += red[threadIdx.x + s].x;
            red[threadIdx.x].y += red[threadIdx.x + s].y;
        }
        __syncthreads();
    }

    // deterministic last-block finish
    if (threadIdx.x == 0) {
        int slot = blockIdx.y * VCHUNKS + blockIdx.x;
        g_part_d[slot] = red[0].x;
        g_part_p[slot] = red[0].y;
        __threadfence();
        unsigned t = atomicAdd(&g_ticket, 1);
        if (t == NPART - 1) {
            __threadfence();
            float sd = 0.0f, sp = 0.0f;
            for (int i = 0; i < NPART; i++) { sd += g_part_d[i]; sp += g_part_p[i]; }
            out[0] = sd / (float)(NB * NV * NKNN);
            if (out_size > 1) out[1] = sp / (float)(NB * NV);
            g_ticket = 0;   // reset for next graph replay
        }
    }
}

// ---------------- launch ----------------
extern "C" void kernel_launch(void* const* d_in, const int* in_sizes, int n_in,
                              void* d_out, int out_size) {
    const float* verts        = (const float*)d_in[0];  // (16,778,3)
    const float* anchor_verts = (const float*)d_in[1];  // (16,32,3)
    const float* obj_pts      = (const float*)d_in[2];  // (16,8192,3)
    const float* cg           = (const float*)d_in[3];  // (16,32,12)
    const float* obj_normals  = (const float*)d_in[4];  // (16,8192,6)
    const float* init_verts   = (const float*)d_in[5];  // (778,3)
    const float* init_anchors = (const float*)d_in[6];  // (32,3)
    (void)in_sizes; (void)n_in;

    k_setup<<<12, 128>>>(init_verts, init_anchors, cg, anchor_verts);
    k_weights<<<(NB * NV + 127) / 128, 128>>>(verts);
    dim3 grid(VCHUNKS, NB, OSPLIT);
    k_main<<<grid, BLK>>>(verts, obj_pts, obj_normals);
    dim3 mgrid(VCHUNKS, NB, 1);
    k_merge<<<mgrid, MBLK>>>(verts, obj_normals, (float*)d_out, out_size);
}

// round 14
// speedup vs baseline: 1.6027x; 1.6027x over previous
#include <cuda_runtime.h>
#include <math.h>

#define NB 16      // batch
#define NV 778     // verts
#define NO 8192    // obj points
#define NG 32      // groups
#define NKNN 5     // K
#define BLK 128    // threads per block
#define VCHUNKS 7  // ceil(778/128)
#define VP (VCHUNKS * BLK)     // 896 padded vertices
#define OSPLIT 16
#define OTILE (NO / OSPLIT)    // 512 points per block
#define HTILE (OTILE / 2)      // 256 pairs
#define NPART (VCHUNKS * NB)   // 112 partial slots

#define C3LOG2PI 5.5136313438f  // fp32(3.0 * log(2*pi))

// ---------------- device scratch (no allocation allowed) ----------------
__device__ int      g_gid[NV];
__device__ float    g_prep[NB * NG * 10];
__device__ int      g_active[NG];
__device__ unsigned g_segmin[NB * NG];
__device__ unsigned g_segmax[NB * NG];
__device__ float    g_w[NB * NV];
// coalesced split partials: k5[((os*NB+b)*5+i)*VP+vp], bs/bi[(os*NB+b)*VP+vp]
__device__ float    g_k5[OSPLIT * NB * 5 * VP];
__device__ float    g_bs[OSPLIT * NB * VP];
__device__ int      g_bi[OSPLIT * NB * VP];
__device__ float    g_part_d[NPART];
__device__ float    g_part_p[NPART];
__device__ unsigned g_ticket = 0;

// ---------------- packed f32x2 helpers (sm_103a FFMA2) ----------------
__device__ __forceinline__ unsigned long long pk2(float a, float b) {
    unsigned long long r;
    asm("mov.b64 %0, {%1,%2};" : "=l"(r) : "f"(a), "f"(b));
    return r;
}
__device__ __forceinline__ unsigned long long fma2(unsigned long long a,
                                                   unsigned long long b,
                                                   unsigned long long c) {
    unsigned long long d;
    asm("fma.rn.f32x2 %0, %1, %2, %3;" : "=l"(d) : "l"(a), "l"(b), "l"(c));
    return d;
}
__device__ __forceinline__ void upk2(unsigned long long r, float& lo, float& hi) {
    asm("mov.b64 {%0,%1}, %2;" : "=f"(lo), "=f"(hi) : "l"(r));
}

__device__ __forceinline__ void ins5(float s, float& k0, float& k1, float& k2,
                                     float& k3, float& k4) {
    k4 = s;
    if (k4 < k3) { float t = k3; k3 = k4; k4 = t;
        if (k3 < k2) { t = k2; k2 = k3; k3 = t;
            if (k2 < k1) { t = k1; k1 = k2; k2 = t;
                if (k1 < k0) { t = k0; k0 = k1; k1 = t; } } } }
}

// ---------------- kernel 1: parallel setup (gid | prep | active) ----------------
// grid 12 x 128: blocks 0-6 gid, blocks 7-10 Cholesky prep + seg init, block 11 active flags
__global__ void __launch_bounds__(128) k_setup(const float* __restrict__ init_verts,
                                               const float* __restrict__ init_anchors,
                                               const float* __restrict__ cg,
                                               const float* __restrict__ anchor_verts) {
    int bid = blockIdx.x;
    int t = threadIdx.x;

    if (bid < 7) {
        // ---- vertex -> group assignment ----
        int v = bid * 128 + t;
        if (v < NV) {
            float ax = init_verts[3 * v + 0];
            float ay = init_verts[3 * v + 1];
            float az = init_verts[3 * v + 2];
            float a2 = ax * ax + ay * ay + az * az;
            float best = INFINITY;
            int bi = 0;
            #pragma unroll
            for (int g = 0; g < NG; g++) {
                float bx = init_anchors[3 * g + 0];
                float by = init_anchors[3 * g + 1];
                float bz = init_anchors[3 * g + 2];
                float b2 = bx * bx + by * by + bz * bz;
                float d2 = a2 + b2 - 2.0f * (ax * bx + ay * by + az * bz);
                if (d2 < best) { best = d2; bi = g; }   // strict < : first min
            }
            g_gid[v] = bi;
        }
    } else if (bid < 11) {
        // ---- per-(b,g) Cholesky prep + segment init ----
        int idx = (bid - 7) * 128 + t;   // 0..511
        g_segmin[idx] = 0x7F800000u;     // +inf
        g_segmax[idx] = 0u;              // +0.0

        const float* c = cg + idx * 12;
        float c00 = c[3], c10 = c[6], c11 = c[7], c20 = c[9], c21 = c[10], c22 = c[11];
        float L00 = sqrtf(c00);
        float L10 = c10 / L00;
        float L20 = c20 / L00;
        float L11 = sqrtf(c11 - L10 * L10);
        float L21 = (c21 - L20 * L10) / L11;
        float L22 = sqrtf(c22 - L20 * L20 - L21 * L21);
        float hld = logf(L00) + logf(L11) + logf(L22);

        float* P = g_prep + idx * 10;
        P[0] = L00; P[1] = L10; P[2] = L11;
        P[3] = L20; P[4] = L21; P[5] = L22;
        P[6] = c[0] + anchor_verts[idx * 3 + 0];
        P[7] = c[1] + anchor_verts[idx * 3 + 1];
        P[8] = c[2] + anchor_verts[idx * 3 + 2];
        P[9] = hld;
    } else {
        // ---- active flags: direct per-g reduction (no atomics, no reset race) ----
        if (t < NG) {
            int act = 0;
            for (int b = 0; b < NB; b++) {
                const float* c = cg + (b * NG + t) * 12;
                #pragma unroll
                for (int i = 0; i < 12; i++) act |= (fabsf(c[i]) > 1e-9f);
            }
            g_active[t] = act;
        }
    }
}

// ---------------- kernel 2: Gaussian weights + segment min/max ----------------
__global__ void k_weights(const float* __restrict__ verts) {
    int i = blockIdx.x * blockDim.x + threadIdx.x;
    if (i >= NB * NV) return;
    int b = i / NV;
    int v = i % NV;
    int g = g_gid[v];
    const float* P = g_prep + (b * NG + g) * 10;
    float dx = verts[3 * i + 0] - P[6];
    float dy = verts[3 * i + 1] - P[7];
    float dz = verts[3 * i + 2] - P[8];
    float y0 = dx / P[0];
    float y1 = (dy - P[1] * y0) / P[2];
    float y2 = (dz - P[3] * y0 - P[4] * y1) / P[5];
    float maha = y0 * y0 + y1 * y1 + y2 * y2;
    float logp = -0.5f * (maha + C3LOG2PI) - P[9];
    float w = expf(logp);
    g_w[i] = w;
    unsigned wb = __float_as_uint(w);
    atomicMin(&g_segmin[b * NG + g], wb);
    atomicMax(&g_segmax[b * NG + g], wb);
}

// ---------------- kernel 3: split KNN + nearest-normal sweep (R5 body: float4 + pk2) ----------------
__global__ void __launch_bounds__(BLK) k_main(const float* __restrict__ verts,
                                              const float* __restrict__ obj_pts,
                                              const float* __restrict__ obj_nrm) {
    // paired layouts: A=(x'0,x'1,y'0,y'1)  B=(z'0,z'1,w0,w1), x' = -2x
    __shared__ float4 sA[HTILE], sB[HTILE];   // obj points
    __shared__ float4 sC[HTILE], sD[HTILE];   // normal points

    int b  = blockIdx.y;
    int os = blockIdx.z;
    int vp = blockIdx.x * BLK + threadIdx.x;

    float ax = 0.f, ay = 0.f, az = 0.f;
    if (vp < NV) {
        int i = b * NV + vp;
        ax = verts[3 * i + 0];
        ay = verts[3 * i + 1];
        az = verts[3 * i + 2];
    }

    int base = os * OTILE;
    const float* OP = obj_pts + (size_t)b * NO * 3;
    const float* ON = obj_nrm + (size_t)b * NO * 6;

    for (int j = threadIdx.x; j < OTILE; j += BLK) {
        int o = base + j;
        int h = j >> 1, e = j & 1;
        float x = OP[3 * o + 0], y = OP[3 * o + 1], z = OP[3 * o + 2];
        float* A = (float*)&sA[h];
        float* Bp = (float*)&sB[h];
        A[e]      = -2.0f * x;
        A[2 + e]  = -2.0f * y;
        Bp[e]     = -2.0f * z;
        Bp[2 + e] = x * x + y * y + z * z;
        float nx = ON[6 * o + 0], ny = ON[6 * o + 1], nz = ON[6 * o + 2];
        float* C = (float*)&sC[h];
        float* D = (float*)&sD[h];
        C[e]     = -2.0f * nx;
        C[2 + e] = -2.0f * ny;
        D[e]     = -2.0f * nz;
        D[2 + e] = nx * nx + ny * ny + nz * nz;
    }
    __syncthreads();

    unsigned long long AX = pk2(ax, ax), AY = pk2(ay, ay), AZ = pk2(az, az);

    float k0 = INFINITY, k1 = INFINITY, k2 = INFINITY, k3 = INFINITY, k4 = INFINITY;
    float best = INFINITY;
    int   bidx = base;

    #pragma unroll 4
    for (int h = 0; h < HTILE; h++) {
        float4 A = sA[h];      // broadcast LDS.128
        float4 Bv = sB[h];
        unsigned long long r = fma2(AZ, pk2(Bv.x, Bv.y), pk2(Bv.z, Bv.w));
        r = fma2(AY, pk2(A.z, A.w), r);
        r = fma2(AX, pk2(A.x, A.y), r);
        float s0, s1; upk2(r, s0, s1);
        float m = fminf(s0, s1);
        if (m < k4) {                       // rare
            if (s0 < k4) ins5(s0, k0, k1, k2, k3, k4);
            if (s1 < k4) ins5(s1, k0, k1, k2, k3, k4);
        }

        float4 C = sC[h];
        float4 Dv = sD[h];
        unsigned long long q = fma2(AZ, pk2(Dv.x, Dv.y), pk2(Dv.z, Dv.w));
        q = fma2(AY, pk2(C.z, C.w), q);
        q = fma2(AX, pk2(C.x, C.y), q);
        float n0, n1; upk2(q, n0, n1);
        float mn = fminf(n0, n1);
        if (mn < best) {                    // rare
            if (n0 < best) { best = n0; bidx = base + 2 * h; }
            if (n1 < best) { best = n1; bidx = base + 2 * h + 1; }
        }
    }

    // coalesced split-partial stores
    int sbase = (os * NB + b);
    float* K = g_k5 + (size_t)sbase * 5 * VP + vp;
    K[0 * VP] = k0; K[1 * VP] = k1; K[2 * VP] = k2; K[3 * VP] = k3; K[4 * VP] = k4;
    g_bs[(size_t)sbase * VP + vp] = best;
    g_bi[(size_t)sbase * VP + vp] = bidx;
}

// ---------------- kernel 4: merge + epilogue + deterministic finish (R6 body) ----------------
__global__ void __launch_bounds__(BLK) k_merge(const float* __restrict__ verts,
                                               const float* __restrict__ obj_nrm,
                                               float* __restrict__ out, int out_size) {
    int b  = blockIdx.y;
    int vp = blockIdx.x * BLK + threadIdx.x;   // 0..895
    bool act = (vp < NV);

    // ---- issue ALL partial loads up front (one latency wave) ----
    float kb[OSPLIT * 5];
    float bsb[OSPLIT];
    int   bib[OSPLIT];
    #pragma unroll
    for (int os = 0; os < OSPLIT; os++) {
        const float* K = g_k5 + (size_t)(os * NB + b) * 5 * VP + vp;
        #pragma unroll
        for (int i = 0; i < 5; i++) kb[os * 5 + i] = K[i * VP];   // coalesced
    }
    #pragma unroll
    for (int os = 0; os < OSPLIT; os++) {
        size_t sl = (size_t)(os * NB + b) * VP + vp;
        bsb[os] = g_bs[sl];
        bib[os] = g_bi[sl];
    }

    float ax = 0.f, ay = 0.f, az = 0.f, eff = 0.f;
    if (act) {
        int i = b * NV + vp;
        ax = verts[3 * i + 0];
        ay = verts[3 * i + 1];
        az = verts[3 * i + 2];
        int g = g_gid[vp];
        float w  = g_w[i];
        float mn = __uint_as_float(g_segmin[b * NG + g]);
        float mx = __uint_as_float(g_segmax[b * NG + g]);
        float wn = (w - mn) / (mx - mn);
        wn  = (wn > 0.01f) ? wn : 0.0f;     // NaN -> false -> 0 (matches jnp.where)
        eff = g_active[g] ? wn : 0.0f;
    }

    // merge top-5 over 80 register values (ascending os,i preserves tie semantics)
    float k0 = INFINITY, k1 = INFINITY, k2 = INFINITY, k3 = INFINITY, k4 = INFINITY;
    #pragma unroll
    for (int j = 0; j < OSPLIT * 5; j++) {
        float s = kb[j];
        if (s < k4) ins5(s, k0, k1, k2, k3, k4);
    }

    // merge argmin (strict < keeps lowest split -> lowest global index on ties)
    float best = INFINITY; int bidx = 0;
    #pragma unroll
    for (int os = 0; os < OSPLIT; os++) {
        if (bsb[os] < best) { best = bsb[os]; bidx = bib[os]; }
    }

    float va2 = ax * ax + ay * ay + az * az;
    float ksum = sqrtf(fmaxf(k0 + va2, 0.0f))
               + sqrtf(fmaxf(k1 + va2, 0.0f))
               + sqrtf(fmaxf(k2 + va2, 0.0f))
               + sqrtf(fmaxf(k3 + va2, 0.0f))
               + sqrtf(fmaxf(k4 + va2, 0.0f));
    float dpart = eff * ksum;

    float ppart = 0.0f;
    if (act) {
        const float* nn = obj_nrm + ((size_t)b * NO + bidx) * 6;
        float px = nn[0], py = nn[1], pz = nn[2];
        float nx = nn[3], ny = nn[4], nz = nn[5];
        float rx = px - 0.002f * nx;
        float ry = py - 0.002f * ny;
        float rz = pz - 0.002f * nz;
        float dp = nx * (ax - rx) + ny * (ay - ry) + nz * (az - rz);
        ppart = fmaxf(-dp, 0.0f);
    }

    __shared__ float2 red[BLK];
    red[threadIdx.x] = make_float2(dpart, ppart);
    __syncthreads();
    for (int s = BLK / 2; s > 0; s >>= 1) {
        if (threadIdx.x < s) {
            red[threadIdx.x].x += red[threadIdx.x + s].x;
            red[threadIdx.x].y += red[threadIdx.x + s].y;
        }
        __syncthreads();
    }

    // deterministic last-block finish
    if (threadIdx.x == 0) {
        int slot = blockIdx.y * VCHUNKS + blockIdx.x;
        g_part_d[slot] = red[0].x;
        g_part_p[slot] = red[0].y;
        __threadfence();
        unsigned t = atomicAdd(&g_ticket, 1);
        if (t == NPART - 1) {
            __threadfence();
            float sd = 0.0f, sp = 0.0f;
            for (int i = 0; i < NPART; i++) { sd += g_part_d[i]; sp += g_part_p[i]; }
            out[0] = sd / (float)(NB * NV * NKNN);
            if (out_size > 1) out[1] = sp / (float)(NB * NV);
            g_ticket = 0;   // reset for next graph replay
        }
    }
}

// ---------------- launch ----------------
extern "C" void kernel_launch(void* const* d_in, const int* in_sizes, int n_in,
                              void* d_out, int out_size) {
    const float* verts        = (const float*)d_in[0];  // (16,778,3)
    const float* anchor_verts = (const float*)d_in[1];  // (16,32,3)
    const float* obj_pts      = (const float*)d_in[2];  // (16,8192,3)
    const float* cg           = (const float*)d_in[3];  // (16,32,12)
    const float* obj_normals  = (const float*)d_in[4];  // (16,8192,6)
    const float* init_verts   = (const float*)d_in[5];  // (778,3)
    const float* init_anchors = (const float*)d_in[6];  // (32,3)
    (void)in_sizes; (void)n_in;

    k_setup<<<12, 128>>>(init_verts, init_anchors, cg, anchor_verts);
    k_weights<<<(NB * NV + 127) / 128, 128>>>(verts);
    dim3 grid(VCHUNKS, NB, OSPLIT);
    k_main<<<grid, BLK>>>(verts, obj_pts, obj_normals);
    dim3 mgrid(VCHUNKS, NB, 1);
    k_merge<<<mgrid, BLK>>>(verts, obj_normals, (float*)d_out, out_size);
}

// round 15
// speedup vs baseline: 1.7679x; 1.1031x over previous
#include <cuda_runtime.h>
#include <math.h>

#define NB 16      // batch
#define NV 778     // verts
#define NO 8192    // obj points
#define NG 32      // groups
#define NKNN 5     // K
#define BLK 128    // threads per block
#define VCHUNKS 7  // ceil(778/128)
#define VP (VCHUNKS * BLK)     // 896 padded vertices
#define OSPLIT 8
#define OTILE (NO / OSPLIT)    // 1024 points per block
#define NPART (VCHUNKS * NB)   // 112 partial slots

#define C3LOG2PI 5.5136313438f  // fp32(3.0 * log(2*pi))

// ---------------- device scratch (no allocation allowed) ----------------
__device__ int      g_gid[NV];
__device__ float    g_prep[NB * NG * 10];
__device__ int      g_active[NG];
__device__ unsigned g_segmin[NB * NG];
__device__ unsigned g_segmax[NB * NG];
__device__ float    g_w[NB * NV];
__device__ float    g_k5[NB * VP * OSPLIT * 5];   // per-split top-5 scores (row layout)
__device__ float    g_bs[NB * VP * OSPLIT];       // per-split best normal score
__device__ int      g_bi[NB * VP * OSPLIT];       // per-split best normal index
__device__ float    g_part_d[NPART];
__device__ float    g_part_p[NPART];
__device__ unsigned g_ticket = 0;

#define INS5(s) do {                                                    \
    k4 = (s);                                                           \
    if (k4 < k3) { float _t = k3; k3 = k4; k4 = _t;                     \
        if (k3 < k2) { _t = k2; k2 = k3; k3 = _t;                       \
            if (k2 < k1) { _t = k1; k1 = k2; k2 = _t;                   \
                if (k1 < k0) { _t = k0; k0 = k1; k1 = _t; } } } }       \
} while (0)

// ---------------- kernel 1: parallel setup (gid | prep | active) ----------------
// grid 12 x 128: blocks 0-6 gid, blocks 7-10 Cholesky prep + seg init, block 11 active flags
__global__ void __launch_bounds__(128) k_setup(const float* __restrict__ init_verts,
                                               const float* __restrict__ init_anchors,
                                               const float* __restrict__ cg,
                                               const float* __restrict__ anchor_verts) {
    int bid = blockIdx.x;
    int t = threadIdx.x;

    if (bid < 7) {
        // ---- vertex -> group assignment ----
        int v = bid * 128 + t;
        if (v < NV) {
            float ax = init_verts[3 * v + 0];
            float ay = init_verts[3 * v + 1];
            float az = init_verts[3 * v + 2];
            float a2 = ax * ax + ay * ay + az * az;
            float best = INFINITY;
            int bi = 0;
            #pragma unroll
            for (int g = 0; g < NG; g++) {
                float bx = init_anchors[3 * g + 0];
                float by = init_anchors[3 * g + 1];
                float bz = init_anchors[3 * g + 2];
                float b2 = bx * bx + by * by + bz * bz;
                float d2 = a2 + b2 - 2.0f * (ax * bx + ay * by + az * bz);
                if (d2 < best) { best = d2; bi = g; }   // strict < : first min == argmin
            }
            g_gid[v] = bi;
        }
    } else if (bid < 11) {
        // ---- per-(b,g) Cholesky prep + segment init ----
        int idx = (bid - 7) * 128 + t;   // 0..511
        g_segmin[idx] = 0x7F800000u;     // +inf
        g_segmax[idx] = 0u;              // +0.0

        const float* c = cg + idx * 12;
        float c00 = c[3], c10 = c[6], c11 = c[7], c20 = c[9], c21 = c[10], c22 = c[11];
        float L00 = sqrtf(c00);
        float L10 = c10 / L00;
        float L20 = c20 / L00;
        float L11 = sqrtf(c11 - L10 * L10);
        float L21 = (c21 - L20 * L10) / L11;
        float L22 = sqrtf(c22 - L20 * L20 - L21 * L21);
        float hld = logf(L00) + logf(L11) + logf(L22);

        float* P = g_prep + idx * 10;
        P[0] = 1.0f / L00;
        P[1] = L10;
        P[2] = 1.0f / L11;
        P[3] = L20;
        P[4] = L21;
        P[5] = 1.0f / L22;
        P[6] = c[0] + anchor_verts[idx * 3 + 0];
        P[7] = c[1] + anchor_verts[idx * 3 + 1];
        P[8] = c[2] + anchor_verts[idx * 3 + 2];
        P[9] = hld;
    } else {
        // ---- active flags: direct per-g reduction (no atomics, no reset race) ----
        if (t < NG) {
            int act = 0;
            for (int b = 0; b < NB; b++) {
                const float* c = cg + (b * NG + t) * 12;
                #pragma unroll
                for (int i = 0; i < 12; i++) act |= (fabsf(c[i]) > 1e-9f);
            }
            g_active[t] = act;
        }
    }
}

// ---------------- kernel 2: Gaussian weights + segment min/max (champion body) ----------------
__global__ void k_weights(const float* __restrict__ verts) {
    int i = blockIdx.x * blockDim.x + threadIdx.x;
    if (i >= NB * NV) return;
    int b = i / NV;
    int v = i % NV;
    int g = g_gid[v];
    const float* P = g_prep + (b * NG + g) * 10;
    float dx = verts[3 * i + 0] - P[6];
    float dy = verts[3 * i + 1] - P[7];
    float dz = verts[3 * i + 2] - P[8];
    float y0 = dx * P[0];
    float y1 = (dy - P[1] * y0) * P[2];
    float y2 = (dz - P[3] * y0 - P[4] * y1) * P[5];
    float maha = y0 * y0 + y1 * y1 + y2 * y2;
    float logp = -0.5f * (maha + C3LOG2PI) - P[9];
    float w = expf(logp);          // strictly positive
    g_w[i] = w;
    unsigned wb = __float_as_uint(w);
    atomicMin(&g_segmin[b * NG + g], wb);
    atomicMax(&g_segmax[b * NG + g], wb);
}

// ---------------- kernel 3: split KNN + nearest-normal sweep (champion body) ----------------
__global__ void __launch_bounds__(BLK) k_main(const float* __restrict__ verts,
                                              const float* __restrict__ obj_pts,
                                              const float* __restrict__ obj_nrm) {
    __shared__ float4 sp[OTILE];   // (-2x,-2y,-2z, |p|^2) obj point
    __shared__ float4 sq[OTILE];   // (-2x,-2y,-2z, |p|^2) normal point

    int b  = blockIdx.y;
    int os = blockIdx.z;
    int vp = blockIdx.x * BLK + threadIdx.x;   // padded vertex index

    float ax = 0.f, ay = 0.f, az = 0.f;
    if (vp < NV) {
        int i = b * NV + vp;
        ax = verts[3 * i + 0];
        ay = verts[3 * i + 1];
        az = verts[3 * i + 2];
    }

    int base = os * OTILE;
    const float* OP = obj_pts + (size_t)b * NO * 3;
    const float* ON = obj_nrm + (size_t)b * NO * 6;

    for (int j = threadIdx.x; j < OTILE; j += BLK) {
        int o = base + j;
        float x = OP[3 * o + 0], y = OP[3 * o + 1], z = OP[3 * o + 2];
        sp[j] = make_float4(-2.0f * x, -2.0f * y, -2.0f * z, x * x + y * y + z * z);
        float nx = ON[6 * o + 0], ny = ON[6 * o + 1], nz = ON[6 * o + 2];
        sq[j] = make_float4(-2.0f * nx, -2.0f * ny, -2.0f * nz, nx * nx + ny * ny + nz * nz);
    }
    __syncthreads();

    float k0 = INFINITY, k1 = INFINITY, k2 = INFINITY, k3 = INFINITY, k4 = INFINITY;
    float best = INFINITY;
    int   bidx = base;

    #pragma unroll 4
    for (int j = 0; j < OTILE; j++) {
        float4 p = sp[j];   // broadcast LDS.128 — all lanes same address
        float s = fmaf(ax, p.x, fmaf(ay, p.y, fmaf(az, p.z, p.w)));
        if (s < k4) {
            k4 = s;
            if (k4 < k3) { float t = k3; k3 = k4; k4 = t;
                if (k3 < k2) { t = k2; k2 = k3; k3 = t;
                    if (k2 < k1) { t = k1; k1 = k2; k2 = t;
                        if (k1 < k0) { t = k0; k0 = k1; k1 = t; } } } }
        }
        float4 q = sq[j];
        float sn = fmaf(ax, q.x, fmaf(ay, q.y, fmaf(az, q.z, q.w)));
        if (sn < best) { best = sn; bidx = base + j; }
    }

    int slot = (b * VP + vp) * OSPLIT + os;
    float* K = g_k5 + slot * 5;
    K[0] = k0; K[1] = k1; K[2] = k2; K[3] = k3; K[4] = k4;
    g_bs[slot] = best;
    g_bi[slot] = bidx;
}

// ---------------- kernel 4: merge + epilogue + deterministic finish (champion body + ticket) ----------------
__global__ void __launch_bounds__(BLK) k_merge(const float* __restrict__ verts,
                                               const float* __restrict__ obj_nrm,
                                               float* __restrict__ out, int out_size) {
    int b  = blockIdx.y;
    int vp = blockIdx.x * BLK + threadIdx.x;
    bool act = (vp < NV);

    float ax = 0.f, ay = 0.f, az = 0.f, eff = 0.f;
    if (act) {
        int i = b * NV + vp;
        ax = verts[3 * i + 0];
        ay = verts[3 * i + 1];
        az = verts[3 * i + 2];
        int g = g_gid[vp];
        float w  = g_w[i];
        float mn = __uint_as_float(g_segmin[b * NG + g]);
        float mx = __uint_as_float(g_segmax[b * NG + g]);
        float wn = (w - mn) / (mx - mn);
        wn  = (wn > 0.01f) ? wn : 0.0f;     // NaN compare -> false -> 0
        eff = g_active[g] ? wn : 0.0f;
    }

    int slot0 = (b * VP + vp) * OSPLIT;

    // merge 8 x top-5 (ascending split order preserves first-index ties)
    float k0 = INFINITY, k1 = INFINITY, k2 = INFINITY, k3 = INFINITY, k4 = INFINITY;
    #pragma unroll
    for (int os = 0; os < OSPLIT; os++) {
        const float* K = g_k5 + (slot0 + os) * 5;
        #pragma unroll
        for (int i = 0; i < 5; i++) {
            float s = K[i];
            if (s < k4) { INS5(s); }
        }
    }

    // merge argmin (strict < keeps lowest split/index on ties)
    float best = INFINITY; int bidx = 0;
    #pragma unroll
    for (int os = 0; os < OSPLIT; os++) {
        float s = g_bs[slot0 + os];
        if (s < best) { best = s; bidx = g_bi[slot0 + os]; }
    }

    float va2 = ax * ax + ay * ay + az * az;
    float ksum = sqrtf(fmaxf(k0 + va2, 0.0f))
               + sqrtf(fmaxf(k1 + va2, 0.0f))
               + sqrtf(fmaxf(k2 + va2, 0.0f))
               + sqrtf(fmaxf(k3 + va2, 0.0f))
               + sqrtf(fmaxf(k4 + va2, 0.0f));
    float dpart = eff * ksum;

    float ppart = 0.0f;
    if (act) {
        const float* nn = obj_nrm + ((size_t)b * NO + bidx) * 6;
        float px = nn[0], py = nn[1], pz = nn[2];
        float nx = nn[3], ny = nn[4], nz = nn[5];
        float rx = px - 0.002f * nx;
        float ry = py - 0.002f * ny;
        float rz = pz - 0.002f * nz;
        float dp = nx * (ax - rx) + ny * (ay - ry) + nz * (az - rz);
        ppart = fmaxf(-dp, 0.0f);
    }

    __shared__ float2 red[BLK];
    red[threadIdx.x] = make_float2(dpart, ppart);
    __syncthreads();
    for (int s = BLK / 2; s > 0; s >>= 1) {
        if (threadIdx.x < s) {
            red[threadIdx.x].x += red[threadIdx.x + s].x;
            red[threadIdx.x].y += red[threadIdx.x + s].y;
        }
        __syncthreads();
    }

    // deterministic last-block finish (fixed-order final sum)
    if (threadIdx.x == 0) {
        int slot = blockIdx.y * VCHUNKS + blockIdx.x;
        g_part_d[slot] = red[0].x;
        g_part_p[slot] = red[0].y;
        __threadfence();
        unsigned t = atomicAdd(&g_ticket, 1);
        if (t == NPART - 1) {
            __threadfence();
            float sd = 0.0f, sp = 0.0f;
            for (int i = 0; i < NPART; i++) { sd += g_part_d[i]; sp += g_part_p[i]; }
            out[0] = sd / (float)(NB * NV * NKNN);
            if (out_size > 1) out[1] = sp / (float)(NB * NV);
            g_ticket = 0;   // reset for next graph replay
        }
    }
}

// ---------------- launch ----------------
extern "C" void kernel_launch(void* const* d_in, const int* in_sizes, int n_in,
                              void* d_out, int out_size) {
    const float* verts        = (const float*)d_in[0];  // (16,778,3)
    const float* anchor_verts = (const float*)d_in[1];  // (16,32,3)
    const float* obj_pts      = (const float*)d_in[2];  // (16,8192,3)
    const float* cg           = (const float*)d_in[3];  // (16,32,12)
    const float* obj_normals  = (const float*)d_in[4];  // (16,8192,6)
    const float* init_verts   = (const float*)d_in[5];  // (778,3)
    const float* init_anchors = (const float*)d_in[6];  // (32,3)
    (void)in_sizes; (void)n_in;

    k_setup<<<12, 128>>>(init_verts, init_anchors, cg, anchor_verts);
    k_weights<<<(NB * NV + 127) / 128, 128>>>(verts);
    dim3 grid(VCHUNKS, NB, OSPLIT);
    k_main<<<grid, BLK>>>(verts, obj_pts, obj_normals);
    dim3 mgrid(VCHUNKS, NB, 1);
    k_merge<<<mgrid, BLK>>>(verts, obj_normals, (float*)d_out, out_size);
}